// round 1
// baseline (speedup 1.0000x reference)
#include <cuda_runtime.h>
#include <math.h>

#define HID   4096
#define IH    8192
#define VOCAB 32000

// Scratch (allocation-free: __device__ globals)
__device__ float g_hnew[HID];
__device__ float g_logits[VOCAB];

// ---------------------------------------------------------------------------
// Kernel 1: fused 4-gate GEMV + LSTM cell update.
// One block per hidden row. Each block streams row `row` of W_f/W_i/W_o/W_c
// (4 x 32KB) and dots with combined = [x ; h] (reused from L2).
// ---------------------------------------------------------------------------
__global__ __launch_bounds__(256) void lstm_gates_kernel(
    const float* __restrict__ x,  const float* __restrict__ h,
    const float* __restrict__ c,
    const float* __restrict__ Wf, const float* __restrict__ bf,
    const float* __restrict__ Wi, const float* __restrict__ bi,
    const float* __restrict__ Wo, const float* __restrict__ bo,
    const float* __restrict__ Wc, const float* __restrict__ bc,
    float* __restrict__ out_h, float* __restrict__ out_c)
{
    const int row = blockIdx.x;
    const size_t roff = (size_t)row * IH;
    const float4* __restrict__ wf = (const float4*)(Wf + roff);
    const float4* __restrict__ wi = (const float4*)(Wi + roff);
    const float4* __restrict__ wo = (const float4*)(Wo + roff);
    const float4* __restrict__ wc = (const float4*)(Wc + roff);
    const float4* __restrict__ x4 = (const float4*)x;
    const float4* __restrict__ h4 = (const float4*)h;

    float sf = 0.f, si = 0.f, so = 0.f, sc = 0.f;

    // IH/4 = 2048 float4s; 256 threads -> 8 iterations
    #pragma unroll
    for (int j = threadIdx.x; j < IH / 4; j += 256) {
        float4 cb = (j < HID / 4) ? x4[j] : h4[j - HID / 4];
        float4 a = wf[j];
        float4 b = wi[j];
        float4 d = wo[j];
        float4 e = wc[j];
        sf += a.x * cb.x + a.y * cb.y + a.z * cb.z + a.w * cb.w;
        si += b.x * cb.x + b.y * cb.y + b.z * cb.z + b.w * cb.w;
        so += d.x * cb.x + d.y * cb.y + d.z * cb.z + d.w * cb.w;
        sc += e.x * cb.x + e.y * cb.y + e.z * cb.z + e.w * cb.w;
    }

    // warp reduce 4 accumulators
    #pragma unroll
    for (int off = 16; off > 0; off >>= 1) {
        sf += __shfl_down_sync(0xffffffffu, sf, off);
        si += __shfl_down_sync(0xffffffffu, si, off);
        so += __shfl_down_sync(0xffffffffu, so, off);
        sc += __shfl_down_sync(0xffffffffu, sc, off);
    }

    __shared__ float red[8][4];
    const int wid = threadIdx.x >> 5;
    const int lid = threadIdx.x & 31;
    if (lid == 0) {
        red[wid][0] = sf; red[wid][1] = si;
        red[wid][2] = so; red[wid][3] = sc;
    }
    __syncthreads();

    if (threadIdx.x == 0) {
        float tf = 0.f, ti = 0.f, to = 0.f, tc = 0.f;
        #pragma unroll
        for (int w = 0; w < 8; w++) {
            tf += red[w][0]; ti += red[w][1];
            to += red[w][2]; tc += red[w][3];
        }
        tf += bf[row]; ti += bi[row]; to += bo[row]; tc += bc[row];

        const float fg = 1.f / (1.f + expf(-tf));
        const float ig = 1.f / (1.f + expf(-ti));
        const float og = 1.f / (1.f + expf(-to));
        const float cc = tanhf(tc);

        const float cn = fg * c[row] + ig * cc;
        const float hn = og * tanhf(cn);

        out_c[row]  = cn;
        out_h[row]  = hn;
        g_hnew[row] = hn;
    }
}

// ---------------------------------------------------------------------------
// Kernel 2: output projection GEMV. One block (128 thr) per vocab row.
// ---------------------------------------------------------------------------
__global__ __launch_bounds__(128) void gemv_out_kernel(
    const float* __restrict__ Wout, const float* __restrict__ bout)
{
    const int row = blockIdx.x;
    const float4* __restrict__ w = (const float4*)(Wout + (size_t)row * HID);
    const float4* __restrict__ hv = (const float4*)g_hnew;

    float s = 0.f;
    // HID/4 = 1024 float4s; 128 threads -> 8 iterations
    #pragma unroll
    for (int j = threadIdx.x; j < HID / 4; j += 128) {
        float4 a = w[j];
        float4 b = hv[j];
        s += a.x * b.x + a.y * b.y + a.z * b.z + a.w * b.w;
    }

    #pragma unroll
    for (int off = 16; off > 0; off >>= 1)
        s += __shfl_down_sync(0xffffffffu, s, off);

    __shared__ float red[4];
    const int wid = threadIdx.x >> 5;
    const int lid = threadIdx.x & 31;
    if (lid == 0) red[wid] = s;
    __syncthreads();

    if (threadIdx.x == 0)
        g_logits[row] = red[0] + red[1] + red[2] + red[3] + bout[row];
}

// ---------------------------------------------------------------------------
// Kernel 3: log_softmax over 32000 logits. Single block.
// ---------------------------------------------------------------------------
__global__ __launch_bounds__(1024) void log_softmax_kernel(float* __restrict__ out)
{
    __shared__ float red[32];
    __shared__ float s_max, s_lse;
    const int tid = threadIdx.x;
    const int wid = tid >> 5;
    const int lid = tid & 31;

    // Pass 1: max
    float m = -INFINITY;
    for (int i = tid; i < VOCAB; i += 1024) m = fmaxf(m, g_logits[i]);
    #pragma unroll
    for (int off = 16; off > 0; off >>= 1)
        m = fmaxf(m, __shfl_down_sync(0xffffffffu, m, off));
    if (lid == 0) red[wid] = m;
    __syncthreads();
    if (tid == 0) {
        float mm = red[0];
        #pragma unroll
        for (int w = 1; w < 32; w++) mm = fmaxf(mm, red[w]);
        s_max = mm;
    }
    __syncthreads();
    const float mx = s_max;

    // Pass 2: sum of exp
    float s = 0.f;
    for (int i = tid; i < VOCAB; i += 1024) s += expf(g_logits[i] - mx);
    #pragma unroll
    for (int off = 16; off > 0; off >>= 1)
        s += __shfl_down_sync(0xffffffffu, s, off);
    __syncthreads();
    if (lid == 0) red[wid] = s;
    __syncthreads();
    if (tid == 0) {
        float ss = 0.f;
        #pragma unroll
        for (int w = 0; w < 32; w++) ss += red[w];
        s_lse = mx + logf(ss);
    }
    __syncthreads();
    const float lse = s_lse;

    // Pass 3: write result
    for (int i = tid; i < VOCAB; i += 1024) out[i] = g_logits[i] - lse;
}

// ---------------------------------------------------------------------------
// d_in order (metadata): x, h, c, W_f, b_f, W_i, b_i, W_o, b_o, W_c, b_c,
//                        W_out, b_out
// d_out layout: [logits 32000][h_new 4096][c_new 4096]
// ---------------------------------------------------------------------------
extern "C" void kernel_launch(void* const* d_in, const int* in_sizes, int n_in,
                              void* d_out, int out_size)
{
    const float* x    = (const float*)d_in[0];
    const float* h    = (const float*)d_in[1];
    const float* c    = (const float*)d_in[2];
    const float* Wf   = (const float*)d_in[3];
    const float* bf   = (const float*)d_in[4];
    const float* Wi   = (const float*)d_in[5];
    const float* bi   = (const float*)d_in[6];
    const float* Wo   = (const float*)d_in[7];
    const float* bo   = (const float*)d_in[8];
    const float* Wc   = (const float*)d_in[9];
    const float* bc   = (const float*)d_in[10];
    const float* Wout = (const float*)d_in[11];
    const float* bout = (const float*)d_in[12];

    float* out = (float*)d_out;
    float* out_h = out + VOCAB;         // 32000..36095
    float* out_c = out + VOCAB + HID;   // 36096..40191

    lstm_gates_kernel<<<HID, 256>>>(x, h, c, Wf, bf, Wi, bi, Wo, bo, Wc, bc,
                                    out_h, out_c);
    gemv_out_kernel<<<VOCAB, 128>>>(Wout, bout);
    log_softmax_kernel<<<1, 1024>>>(out);
}